// round 15
// baseline (speedup 1.0000x reference)
#include <cuda_runtime.h>
#include <cuda_bf16.h>
#include <cstdint>

#define NB 8
#define NT 2048
#define NC 768
#define NH 64
#define QS 72   // padded bf16 row stride for SMEM tiles

#define LOG2E 1.44269504f
#define SCLG  0.18033688f   // 0.125 * log2(e)

__device__ __align__(16) __nv_bfloat16 g_qh[NB * NT * NH];
__device__ __align__(16) __nv_bfloat16 g_ql[NB * NT * NH];

__device__ __forceinline__ uint32_t packbf(float e0, float e1) {
    uint32_t r;
    asm("cvt.rn.bf16x2.f32 %0, %1, %2;" : "=r"(r) : "f"(e1), "f"(e0));
    return r;   // lower 16 bits = e0, upper = e1
}
__device__ __forceinline__ float ex2(float x) {
    float r;
    asm("ex2.approx.f32 %0, %1;" : "=f"(r) : "f"(x));
    return r;
}

__device__ __forceinline__ void mma_bf16(float* d, const uint32_t* a,
                                         uint32_t b0, uint32_t b1) {
    asm volatile("mma.sync.aligned.m16n8k16.row.col.f32.bf16.bf16.f32 "
                 "{%0,%1,%2,%3}, {%4,%5,%6,%7}, {%8,%9}, {%0,%1,%2,%3};"
                 : "+f"(d[0]), "+f"(d[1]), "+f"(d[2]), "+f"(d[3])
                 : "r"(a[0]), "r"(a[1]), "r"(a[2]), "r"(a[3]),
                   "r"(b0), "r"(b1));
}

__device__ __forceinline__ void ldsm4(uint32_t* r, uint32_t addr) {
    asm volatile("ldmatrix.sync.aligned.m8n8.x4.shared.b16 {%0,%1,%2,%3}, [%4];"
                 : "=r"(r[0]), "=r"(r[1]), "=r"(r[2]), "=r"(r[3]) : "r"(addr));
}
__device__ __forceinline__ void ldsm4t(uint32_t* r, uint32_t addr) {
    asm volatile("ldmatrix.sync.aligned.m8n8.x4.trans.shared.b16 {%0,%1,%2,%3}, [%4];"
                 : "=r"(r[0]), "=r"(r[1]), "=r"(r[2]), "=r"(r[3]) : "r"(addr));
}

__device__ __forceinline__ void cpa16(uint32_t dst, const void* src) {
    asm volatile("cp.async.cg.shared.global [%0], [%1], 16;"
                 :: "r"(dst), "l"(src) : "memory");
}
#define CPA_COMMIT() asm volatile("cp.async.commit_group;" ::: "memory")
#define CPA_WAIT0()  asm volatile("cp.async.wait_group 0;" ::: "memory")
#define CPA_WAIT1()  asm volatile("cp.async.wait_group 1;" ::: "memory")

// ---------------------------------------------------------------------------
// Projection on tensor cores (bf16x3), cp.async double-buffered, 3-pass mma
// ordering (dep distance 8 over 8 accumulators, one B-frag live at a time).
// ---------------------------------------------------------------------------
#define PX0 0
#define PX1 32768
#define PW0 65536
#define PW1 81920
#define PXH 98304
#define PXL (98304 + 18432)
#define PWH (98304 + 36864)
#define PWL (98304 + 36864 + 9216)
#define PSMEM (98304 + 36864 + 18432)   // 153600

__global__ __launch_bounds__(256) void projT_kernel(const float* __restrict__ x,
                                                    const float* __restrict__ Wq) {
    extern __shared__ char psm[];
    __nv_bfloat16* Xh = (__nv_bfloat16*)(psm + PXH);
    __nv_bfloat16* Xl = (__nv_bfloat16*)(psm + PXL);
    __nv_bfloat16* Wh = (__nv_bfloat16*)(psm + PWH);
    __nv_bfloat16* Wl = (__nv_bfloat16*)(psm + PWL);

    const int tid  = threadIdx.x;
    const int w    = tid >> 5;
    const int lane = tid & 31;
    const int quad = lane >> 3;
    const int l4   = lane >> 2;
    const int l2   = (lane & 3) << 1;
    const int r0   = blockIdx.x * 128;

    const uint32_t Xh_u = (uint32_t)__cvta_generic_to_shared(Xh);
    const uint32_t Xl_u = (uint32_t)__cvta_generic_to_shared(Xl);
    const uint32_t Wh_u = (uint32_t)__cvta_generic_to_shared(Wh);
    const uint32_t Wl_u = (uint32_t)__cvta_generic_to_shared(Wl);
    const uint32_t xf_u[2] = {(uint32_t)__cvta_generic_to_shared(psm + PX0),
                              (uint32_t)__cvta_generic_to_shared(psm + PX1)};
    const uint32_t wf_u[2] = {(uint32_t)__cvta_generic_to_shared(psm + PW0),
                              (uint32_t)__cvta_generic_to_shared(psm + PW1)};
    const float* xf_p[2] = {(const float*)(psm + PX0), (const float*)(psm + PX1)};
    const float* wf_p[2] = {(const float*)(psm + PW0), (const float*)(psm + PW1)};

    const uint32_t xa = ((16 * w + 8 * (quad & 1) + (lane & 7)) * QS + 8 * (quad >> 1)) * 2;
    const uint32_t wb = ((8 * (quad & 1) + (lane & 7)) * QS + 8 * (quad >> 1)) * 2;

    float Oacc[8][4];
#pragma unroll
    for (int nb = 0; nb < 8; nb++)
#pragma unroll
        for (int j = 0; j < 4; j++) Oacc[nb][j] = 0.f;

    {
#pragma unroll
        for (int u = 0; u < 8; u++) {
            int e = tid + u * 256;
            int row = e >> 4, c4 = e & 15;
            cpa16(xf_u[0] + (uint32_t)(row * 64 + c4 * 4) * 4,
                  &x[(size_t)(r0 + row) * NC + c4 * 4]);
        }
#pragma unroll
        for (int u = 0; u < 4; u++) {
            int e = tid + u * 256;
            int row = e >> 4, c4 = e & 15;
            cpa16(wf_u[0] + (uint32_t)(row * 64 + c4 * 4) * 4,
                  &Wq[(size_t)row * NH + c4 * 4]);
        }
        CPA_COMMIT();
    }

    for (int ci = 0; ci < 12; ci++) {
        CPA_WAIT0();
        __syncthreads();
        if (ci + 1 < 12) {
            const int c0n = (ci + 1) * 64;
            const int nb_ = (ci + 1) & 1;
#pragma unroll
            for (int u = 0; u < 8; u++) {
                int e = tid + u * 256;
                int row = e >> 4, c4 = e & 15;
                cpa16(xf_u[nb_] + (uint32_t)(row * 64 + c4 * 4) * 4,
                      &x[(size_t)(r0 + row) * NC + c0n + c4 * 4]);
            }
#pragma unroll
            for (int u = 0; u < 4; u++) {
                int e = tid + u * 256;
                int row = e >> 4, c4 = e & 15;
                cpa16(wf_u[nb_] + (uint32_t)(row * 64 + c4 * 4) * 4,
                      &Wq[(size_t)(c0n + row) * NH + c4 * 4]);
            }
            CPA_COMMIT();
        }

        const float* Xc = xf_p[ci & 1];
        const float* Wc = wf_p[ci & 1];
#pragma unroll
        for (int u = 0; u < 8; u++) {
            int e = tid + u * 256;
            int row = e >> 4, g4 = e & 15;
            float4 v = *(const float4*)&Xc[row * 64 + g4 * 4];
            uint32_t h0 = packbf(v.x, v.y);
            uint32_t h1 = packbf(v.z, v.w);
            uint32_t l0 = packbf(v.x - __uint_as_float(h0 << 16),
                                 v.y - __uint_as_float(h0 & 0xffff0000u));
            uint32_t l1 = packbf(v.z - __uint_as_float(h1 << 16),
                                 v.w - __uint_as_float(h1 & 0xffff0000u));
            *(uint2*)&Xh[row * QS + g4 * 4] = make_uint2(h0, h1);
            *(uint2*)&Xl[row * QS + g4 * 4] = make_uint2(l0, l1);
        }
#pragma unroll
        for (int u = 0; u < 4; u++) {
            int e = tid + u * 256;
            int row = e >> 4, g4 = e & 15;
            float4 v = *(const float4*)&Wc[row * 64 + g4 * 4];
            uint32_t h0 = packbf(v.x, v.y);
            uint32_t h1 = packbf(v.z, v.w);
            uint32_t l0 = packbf(v.x - __uint_as_float(h0 << 16),
                                 v.y - __uint_as_float(h0 & 0xffff0000u));
            uint32_t l1 = packbf(v.z - __uint_as_float(h1 << 16),
                                 v.w - __uint_as_float(h1 & 0xffff0000u));
            *(uint2*)&Wh[row * QS + g4 * 4] = make_uint2(h0, h1);
            *(uint2*)&Wl[row * QS + g4 * 4] = make_uint2(l0, l1);
        }
        __syncthreads();

        uint32_t ah[4][4], al[4][4];
#pragma unroll
        for (int ks = 0; ks < 4; ks++) {
            ldsm4(ah[ks], Xh_u + xa + 32 * ks);
            ldsm4(al[ks], Xl_u + xa + 32 * ks);
        }
        // pass 0: ah x bh
#pragma unroll
        for (int ks = 0; ks < 4; ks++) {
#pragma unroll
            for (int nbp = 0; nbp < 4; nbp++) {
                uint32_t off = wb + (16 * ks * QS + 16 * nbp) * 2;
                uint32_t bh[4];
                ldsm4t(bh, Wh_u + off);
                mma_bf16(Oacc[2 * nbp],     ah[ks], bh[0], bh[1]);
                mma_bf16(Oacc[2 * nbp + 1], ah[ks], bh[2], bh[3]);
            }
        }
        // pass 1: ah x bl
#pragma unroll
        for (int ks = 0; ks < 4; ks++) {
#pragma unroll
            for (int nbp = 0; nbp < 4; nbp++) {
                uint32_t off = wb + (16 * ks * QS + 16 * nbp) * 2;
                uint32_t bl[4];
                ldsm4t(bl, Wl_u + off);
                mma_bf16(Oacc[2 * nbp],     ah[ks], bl[0], bl[1]);
                mma_bf16(Oacc[2 * nbp + 1], ah[ks], bl[2], bl[3]);
            }
        }
        // pass 2: al x bh
#pragma unroll
        for (int ks = 0; ks < 4; ks++) {
#pragma unroll
            for (int nbp = 0; nbp < 4; nbp++) {
                uint32_t off = wb + (16 * ks * QS + 16 * nbp) * 2;
                uint32_t bh[4];
                ldsm4t(bh, Wh_u + off);
                mma_bf16(Oacc[2 * nbp],     al[ks], bh[0], bh[1]);
                mma_bf16(Oacc[2 * nbp + 1], al[ks], bh[2], bh[3]);
            }
        }
    }

    const size_t row0 = (size_t)r0 + 16 * w + l4;
#pragma unroll
    for (int nb = 0; nb < 8; nb++) {
        int c = 8 * nb + l2;
        uint32_t hp0 = packbf(Oacc[nb][0], Oacc[nb][1]);
        uint32_t hp1 = packbf(Oacc[nb][2], Oacc[nb][3]);
        uint32_t lp0 = packbf(Oacc[nb][0] - __uint_as_float(hp0 << 16),
                              Oacc[nb][1] - __uint_as_float(hp0 & 0xffff0000u));
        uint32_t lp1 = packbf(Oacc[nb][2] - __uint_as_float(hp1 << 16),
                              Oacc[nb][3] - __uint_as_float(hp1 & 0xffff0000u));
        *(uint32_t*)&g_qh[row0 * NH + c]       = hp0;
        *(uint32_t*)&g_ql[row0 * NH + c]       = lp0;
        *(uint32_t*)&g_qh[(row0 + 8) * NH + c] = hp1;
        *(uint32_t*)&g_ql[(row0 + 8) * NH + c] = lp1;
    }
}

// ---------------------------------------------------------------------------
// Flash attention: R13 skeleton (pair-scheduled, triple-buffered cp.async,
// QK(it+1) before softmax(it)) with 3-pass mma ordering in QK and PV.
// ---------------------------------------------------------------------------
#define SM_Q      0         // Qh+Ql 18432; reused as merge scratch at tile end
#define SM_REL    18432     // 16384
#define SM_GRP0   34816
#define SM_KBUF   18432     // one buffer: Kh 9216 + Kl 9216
#define SM_GRPSZ  (3 * SM_KBUF)
#define SMEM_BYTES (SM_GRP0 + 2 * SM_GRPSZ)   // 145408

#define QK_TILE(SN, KBASE)                                                     \
    {                                                                          \
        const uint32_t Kh_u_ = (KBASE);                                        \
        const uint32_t Kl_u_ = (KBASE) + 9216;                                 \
        _Pragma("unroll")                                                      \
        for (int nb = 0; nb < 8; nb++)                                         \
            _Pragma("unroll")                                                  \
            for (int j = 0; j < 4; j++) SN[nb][j] = 0.f;                       \
        /* pass 0: qfh x Kh */                                                 \
        _Pragma("unroll")                                                      \
        for (int ks = 0; ks < 4; ks++) {                                       \
            _Pragma("unroll")                                                  \
            for (int nbp = 0; nbp < 4; nbp++) {                                \
                uint32_t off = kqk + (16 * nbp * QS + 16 * ks) * 2;            \
                uint32_t bh[4];                                                \
                ldsm4(bh, Kh_u_ + off);                                        \
                mma_bf16(SN[2 * nbp],     qfh[ks], bh[0], bh[1]);              \
                mma_bf16(SN[2 * nbp + 1], qfh[ks], bh[2], bh[3]);              \
            }                                                                  \
        }                                                                      \
        /* pass 1: qfh x Kl */                                                 \
        _Pragma("unroll")                                                      \
        for (int ks = 0; ks < 4; ks++) {                                       \
            _Pragma("unroll")                                                  \
            for (int nbp = 0; nbp < 4; nbp++) {                                \
                uint32_t off = kqk + (16 * nbp * QS + 16 * ks) * 2;            \
                uint32_t bl[4];                                                \
                ldsm4(bl, Kl_u_ + off);                                        \
                mma_bf16(SN[2 * nbp],     qfh[ks], bl[0], bl[1]);              \
                mma_bf16(SN[2 * nbp + 1], qfh[ks], bl[2], bl[3]);              \
            }                                                                  \
        }                                                                      \
        /* pass 2: qfl x Kh */                                                 \
        _Pragma("unroll")                                                      \
        for (int ks = 0; ks < 4; ks++) {                                       \
            _Pragma("unroll")                                                  \
            for (int nbp = 0; nbp < 4; nbp++) {                                \
                uint32_t off = kqk + (16 * nbp * QS + 16 * ks) * 2;            \
                uint32_t bh[4];                                                \
                ldsm4(bh, Kh_u_ + off);                                        \
                mma_bf16(SN[2 * nbp],     qfl[ks], bh[0], bh[1]);              \
                mma_bf16(SN[2 * nbp + 1], qfl[ks], bh[2], bh[3]);              \
            }                                                                  \
        }                                                                      \
    }

#define FLASH_ITER(IT, SC, SN)                                                 \
    {                                                                          \
        const int kt_ = g + 2 * (IT);                                          \
        const int s0_ = kt_ * 64;                                              \
        CPA_WAIT0();                                                           \
        asm volatile("bar.sync %0, %1;" :: "r"(1 + g), "r"(128) : "memory");   \
        if ((IT) + 2 < nit) {                                                  \
            const int s0n_ = s0_ + 256;                                        \
            _Pragma("unroll")                                                  \
            for (int u = 0; u < 4; u++) {                                      \
                int e = tid128 + u * 128;                                      \
                int row = e >> 3, q4 = e & 7;                                  \
                uint32_t off = (uint32_t)(row * QS + q4 * 8) * 2;              \
                cpa16(kpre + off,        gkh + (size_t)(s0n_ + row) * NH + q4 * 8); \
                cpa16(kpre + 9216 + off, gkl + (size_t)(s0n_ + row) * NH + q4 * 8); \
            }                                                                  \
            CPA_COMMIT();                                                      \
        }                                                                      \
        if ((IT) + 1 < nit) QK_TILE(SN, knxt);                                 \
        /* softmax(it) on SC */                                                \
        {                                                                      \
            const bool diag = (kt_ == tile);                                   \
            const int bb0 = s0_ - t0 + 2047 - rbase;                           \
            const int bb1 = bb0 - 8;                                           \
            _Pragma("unroll")                                                  \
            for (int nb = 0; nb < 8; nb++) {                                   \
                int c0 = 8 * nb + l2;                                          \
                float p0 = ex2(fmaf(SC[nb][0], SCLG, rel_sh[bb0 + c0]));       \
                float p1 = ex2(fmaf(SC[nb][1], SCLG, rel_sh[bb0 + c0 + 1]));   \
                float p2 = ex2(fmaf(SC[nb][2], SCLG, rel_sh[bb1 + c0]));       \
                float p3 = ex2(fmaf(SC[nb][3], SCLG, rel_sh[bb1 + c0 + 1]));   \
                if (diag) {                                                    \
                    if (c0 > rbase)         p0 = 0.f;                          \
                    if (c0 + 1 > rbase)     p1 = 0.f;                          \
                    if (c0 > rbase + 8)     p2 = 0.f;                          \
                    if (c0 + 1 > rbase + 8) p3 = 0.f;                          \
                }                                                              \
                SC[nb][0] = p0; SC[nb][1] = p1; SC[nb][2] = p2; SC[nb][3] = p3;\
                lrow[0] += p0 + p1;                                            \
                lrow[1] += p2 + p3;                                            \
            }                                                                  \
        }                                                                      \
        /* PV(it) on SC using kcur: pack per kb, 3 passes over nbp */          \
        {                                                                      \
            const uint32_t Kh_u_ = kcur;                                       \
            const uint32_t Kl_u_ = kcur + 9216;                                \
            _Pragma("unroll")                                                  \
            for (int kb = 0; kb < 4; kb++) {                                   \
                uint32_t pah[4], pal[4];                                       \
                {                                                              \
                    float p0 = SC[2 * kb][0],     p1 = SC[2 * kb][1];          \
                    float p2 = SC[2 * kb][2],     p3 = SC[2 * kb][3];          \
                    float p4 = SC[2 * kb + 1][0], p5 = SC[2 * kb + 1][1];      \
                    float p6 = SC[2 * kb + 1][2], p7 = SC[2 * kb + 1][3];      \
                    pah[0] = packbf(p0, p1); pah[1] = packbf(p2, p3);          \
                    pah[2] = packbf(p4, p5); pah[3] = packbf(p6, p7);          \
                    pal[0] = packbf(p0 - __uint_as_float(pah[0] << 16),        \
                                    p1 - __uint_as_float(pah[0] & 0xffff0000u)); \
                    pal[1] = packbf(p2 - __uint_as_float(pah[1] << 16),        \
                                    p3 - __uint_as_float(pah[1] & 0xffff0000u)); \
                    pal[2] = packbf(p4 - __uint_as_float(pah[2] << 16),        \
                                    p5 - __uint_as_float(pah[2] & 0xffff0000u)); \
                    pal[3] = packbf(p6 - __uint_as_float(pah[3] << 16),        \
                                    p7 - __uint_as_float(pah[3] & 0xffff0000u)); \
                }                                                              \
                /* pass 0: pah x Vh */                                         \
                _Pragma("unroll")                                              \
                for (int nbp = 0; nbp < 4; nbp++) {                            \
                    uint32_t off = kpv + (16 * kb * QS + 16 * nbp) * 2;        \
                    uint32_t vh[4];                                            \
                    ldsm4t(vh, Kh_u_ + off);                                   \
                    mma_bf16(Oa[2 * nbp],     pah, vh[0], vh[1]);              \
                    mma_bf16(Oa[2 * nbp + 1], pah, vh[2], vh[3]);              \
                }                                                              \
                /* pass 1: pah x Vl */                                         \
                _Pragma("unroll")                                              \
                for (int nbp = 0; nbp < 4; nbp++) {                            \
                    uint32_t off = kpv + (16 * kb * QS + 16 * nbp) * 2;        \
                    uint32_t vl[4];                                            \
                    ldsm4t(vl, Kl_u_ + off);                                   \
                    mma_bf16(Oa[2 * nbp],     pah, vl[0], vl[1]);              \
                    mma_bf16(Oa[2 * nbp + 1], pah, vl[2], vl[3]);              \
                }                                                              \
                /* pass 2: pal x Vh */                                         \
                _Pragma("unroll")                                              \
                for (int nbp = 0; nbp < 4; nbp++) {                            \
                    uint32_t off = kpv + (16 * kb * QS + 16 * nbp) * 2;        \
                    uint32_t vh[4];                                            \
                    ldsm4t(vh, Kh_u_ + off);                                   \
                    mma_bf16(Oa[2 * nbp],     pal, vh[0], vh[1]);              \
                    mma_bf16(Oa[2 * nbp + 1], pal, vh[2], vh[3]);              \
                }                                                              \
            }                                                                  \
        }                                                                      \
        { uint32_t t_ = kcur; kcur = knxt; knxt = kpre; kpre = t_; }           \
    }

__global__ __launch_bounds__(256) void flashT_kernel(const float* __restrict__ rel,
                                                     float* __restrict__ out) {
    extern __shared__ char smraw[];
    __nv_bfloat16* Qh = (__nv_bfloat16*)(smraw + SM_Q);
    __nv_bfloat16* Ql = Qh + 64 * QS;
    float* rel_sh = (float*)(smraw + SM_REL);

    const int tid  = threadIdx.x;
    const int w    = tid >> 5;
    const int lane = tid & 31;
    const int g    = w >> 2;
    const int wi   = w & 3;
    const int quad = lane >> 3;
    const int l4   = lane >> 2;
    const int l2   = (lane & 3) << 1;
    const int tid128 = tid & 127;

    char* gbase = smraw + SM_GRP0 + g * SM_GRPSZ;

    float* Om = (float*)(smraw + SM_Q);            // [64][65] merge scratch
    float* Lm = (float*)(smraw + SM_Q + 16640);    // [64]

    const uint32_t Qh_u = (uint32_t)__cvta_generic_to_shared(Qh);
    const uint32_t Ql_u = (uint32_t)__cvta_generic_to_shared(Ql);

    const uint32_t qa  = ((16 * wi + 8 * (quad & 1) + (lane & 7)) * QS + 8 * (quad >> 1)) * 2;
    const uint32_t kqk = ((8 * (quad >> 1) + (lane & 7)) * QS + 8 * (quad & 1)) * 2;
    const uint32_t kpv = ((8 * (quad & 1) + (lane & 7)) * QS + 8 * (quad >> 1)) * 2;

    const int b    = blockIdx.y;
    const int pair = blockIdx.x;
    const int rbase = 16 * wi + l4;

    for (int i = tid; i < 4095; i += 256) rel_sh[i] = rel[i] * LOG2E;

    const __nv_bfloat16* gkh = &g_qh[(size_t)b * NT * NH];
    const __nv_bfloat16* gkl = &g_ql[(size_t)b * NT * NH];

    for (int pi = 0; pi < 2; pi++) {
        const int tile = (pi == 0) ? (31 - pair) : pair;
        const int t0   = tile * 64;
        __syncthreads();
        // stage Q hi/lo
        {
            const __nv_bfloat16* sh = gkh + (size_t)t0 * NH;
            const __nv_bfloat16* sl = gkl + (size_t)t0 * NH;
#pragma unroll
            for (int u = 0; u < 2; u++) {
                int e   = tid + u * 256;
                int row = e >> 3, q4 = e & 7;
                *(uint4*)&Qh[row * QS + q4 * 8] = *(const uint4*)&sh[row * 64 + q4 * 8];
                *(uint4*)&Ql[row * QS + q4 * 8] = *(const uint4*)&sl[row * 64 + q4 * 8];
            }
        }
        __syncthreads();

        uint32_t qfh[4][4], qfl[4][4];
#pragma unroll
        for (int ks = 0; ks < 4; ks++) {
            ldsm4(qfh[ks], Qh_u + qa + 32 * ks);
            ldsm4(qfl[ks], Ql_u + qa + 32 * ks);
        }

        float Oa[8][4];
#pragma unroll
        for (int nb = 0; nb < 8; nb++)
#pragma unroll
            for (int j = 0; j < 4; j++) Oa[nb][j] = 0.f;
        float lrow[2] = {0.f, 0.f};
        float sa[8][4], sb[8][4];

        const int nit = (g <= tile) ? (((tile - g) >> 1) + 1) : 0;

        uint32_t kcur = (uint32_t)__cvta_generic_to_shared(gbase);
        uint32_t knxt = kcur + SM_KBUF;
        uint32_t kpre = kcur + 2 * SM_KBUF;

        if (nit > 0) {
            const int s00 = g * 64;
#pragma unroll
            for (int u = 0; u < 4; u++) {
                int e = tid128 + u * 128;
                int row = e >> 3, q4 = e & 7;
                uint32_t off = (uint32_t)(row * QS + q4 * 8) * 2;
                cpa16(kcur + off,        gkh + (size_t)(s00 + row) * NH + q4 * 8);
                cpa16(kcur + 9216 + off, gkl + (size_t)(s00 + row) * NH + q4 * 8);
            }
            CPA_COMMIT();
            if (nit > 1) {
                const int s01 = s00 + 128;
#pragma unroll
                for (int u = 0; u < 4; u++) {
                    int e = tid128 + u * 128;
                    int row = e >> 3, q4 = e & 7;
                    uint32_t off = (uint32_t)(row * QS + q4 * 8) * 2;
                    cpa16(knxt + off,        gkh + (size_t)(s01 + row) * NH + q4 * 8);
                    cpa16(knxt + 9216 + off, gkl + (size_t)(s01 + row) * NH + q4 * 8);
                }
                CPA_COMMIT();
                CPA_WAIT1();
            } else {
                CPA_WAIT0();
            }
            asm volatile("bar.sync %0, %1;" :: "r"(1 + g), "r"(128) : "memory");
            QK_TILE(sa, kcur);
        }

        int it = 0;
        while (it < nit) {
            FLASH_ITER(it, sa, sb); it++;
            if (it < nit) { FLASH_ITER(it, sb, sa); it++; }
        }

        // reduce row sums over the 4 lanes sharing a row
        lrow[0] += __shfl_xor_sync(0xffffffffu, lrow[0], 1);
        lrow[0] += __shfl_xor_sync(0xffffffffu, lrow[0], 2);
        lrow[1] += __shfl_xor_sync(0xffffffffu, lrow[1], 1);
        lrow[1] += __shfl_xor_sync(0xffffffffu, lrow[1], 2);

        // ---- merge the two groups' partials (pure addition), write out ----
        __syncthreads();
        if (g == 1) {
#pragma unroll
            for (int nb = 0; nb < 8; nb++) {
                Om[rbase * 65 + 8 * nb + l2]           = Oa[nb][0];
                Om[rbase * 65 + 8 * nb + l2 + 1]       = Oa[nb][1];
                Om[(rbase + 8) * 65 + 8 * nb + l2]     = Oa[nb][2];
                Om[(rbase + 8) * 65 + 8 * nb + l2 + 1] = Oa[nb][3];
            }
            if ((lane & 3) == 0) {
                Lm[rbase]     = lrow[0];
                Lm[rbase + 8] = lrow[1];
            }
        }
        __syncthreads();
        if (g == 0) {
#pragma unroll
            for (int half = 0; half < 2; half++) {
                const int row = rbase + 8 * half;
                const float inv = 1.f / (lrow[half] + Lm[row]);
                float* orow = &out[((size_t)b * NT + t0 + row) * NH];
#pragma unroll
                for (int nb = 0; nb < 8; nb++) {
                    int c = 8 * nb + l2;
                    float2 o2;
                    o2.x = (Oa[nb][2 * half]     + Om[row * 65 + c])     * inv;
                    o2.y = (Oa[nb][2 * half + 1] + Om[row * 65 + c + 1]) * inv;
                    *(float2*)&orow[c] = o2;
                }
            }
        }
    }
}

extern "C" void kernel_launch(void* const* d_in, const int* in_sizes, int n_in,
                              void* d_out, int out_size) {
    const float* x   = (const float*)d_in[0];
    const float* Wq  = (const float*)d_in[1];
    const float* rel = (const float*)d_in[2];
    float* out = (float*)d_out;

    static bool attr_set = false;
    if (!attr_set) {
        cudaFuncSetAttribute(flashT_kernel,
                             cudaFuncAttributeMaxDynamicSharedMemorySize, SMEM_BYTES);
        cudaFuncSetAttribute(projT_kernel,
                             cudaFuncAttributeMaxDynamicSharedMemorySize, PSMEM);
        attr_set = true;
    }

    projT_kernel<<<NB * NT / 128, 256, PSMEM>>>(x, Wq);

    dim3 grid(16, NB);
    flashT_kernel<<<grid, 256, SMEM_BYTES>>>(rel, out);
}

// round 17
// speedup vs baseline: 1.0284x; 1.0284x over previous
#include <cuda_runtime.h>
#include <cuda_bf16.h>
#include <cstdint>

#define NB 8
#define NT 2048
#define NC 768
#define NH 64
#define QS 72   // padded bf16 row stride for SMEM tiles

#define LOG2E 1.44269504f
#define SCLG  0.18033688f   // 0.125 * log2(e)

__device__ __align__(16) __nv_bfloat16 g_qh[NB * NT * NH];
__device__ __align__(16) __nv_bfloat16 g_ql[NB * NT * NH];

__device__ __forceinline__ uint32_t packbf(float e0, float e1) {
    uint32_t r;
    asm("cvt.rn.bf16x2.f32 %0, %1, %2;" : "=r"(r) : "f"(e1), "f"(e0));
    return r;   // lower 16 bits = e0, upper = e1
}
__device__ __forceinline__ float ex2(float x) {
    float r;
    asm("ex2.approx.f32 %0, %1;" : "=f"(r) : "f"(x));
    return r;
}

__device__ __forceinline__ void mma_bf16(float* d, const uint32_t* a,
                                         uint32_t b0, uint32_t b1) {
    asm volatile("mma.sync.aligned.m16n8k16.row.col.f32.bf16.bf16.f32 "
                 "{%0,%1,%2,%3}, {%4,%5,%6,%7}, {%8,%9}, {%0,%1,%2,%3};"
                 : "+f"(d[0]), "+f"(d[1]), "+f"(d[2]), "+f"(d[3])
                 : "r"(a[0]), "r"(a[1]), "r"(a[2]), "r"(a[3]),
                   "r"(b0), "r"(b1));
}

__device__ __forceinline__ void ldsm4(uint32_t* r, uint32_t addr) {
    asm volatile("ldmatrix.sync.aligned.m8n8.x4.shared.b16 {%0,%1,%2,%3}, [%4];"
                 : "=r"(r[0]), "=r"(r[1]), "=r"(r[2]), "=r"(r[3]) : "r"(addr));
}
__device__ __forceinline__ void ldsm4t(uint32_t* r, uint32_t addr) {
    asm volatile("ldmatrix.sync.aligned.m8n8.x4.trans.shared.b16 {%0,%1,%2,%3}, [%4];"
                 : "=r"(r[0]), "=r"(r[1]), "=r"(r[2]), "=r"(r[3]) : "r"(addr));
}

__device__ __forceinline__ void cpa16(uint32_t dst, const void* src) {
    asm volatile("cp.async.cg.shared.global [%0], [%1], 16;"
                 :: "r"(dst), "l"(src) : "memory");
}
#define CPA_COMMIT() asm volatile("cp.async.commit_group;" ::: "memory")
#define CPA_WAIT0()  asm volatile("cp.async.wait_group 0;" ::: "memory")
#define CPA_WAIT1()  asm volatile("cp.async.wait_group 1;" ::: "memory")

// ---------------------------------------------------------------------------
// Projection on tensor cores (bf16x3), cp.async double-buffered (proven R10).
// ---------------------------------------------------------------------------
#define PX0 0
#define PX1 32768
#define PW0 65536
#define PW1 81920
#define PXH 98304
#define PXL (98304 + 18432)
#define PWH (98304 + 36864)
#define PWL (98304 + 36864 + 9216)
#define PSMEM (98304 + 36864 + 18432)   // 153600

__global__ __launch_bounds__(256) void projT_kernel(const float* __restrict__ x,
                                                    const float* __restrict__ Wq) {
    extern __shared__ char psm[];
    __nv_bfloat16* Xh = (__nv_bfloat16*)(psm + PXH);
    __nv_bfloat16* Xl = (__nv_bfloat16*)(psm + PXL);
    __nv_bfloat16* Wh = (__nv_bfloat16*)(psm + PWH);
    __nv_bfloat16* Wl = (__nv_bfloat16*)(psm + PWL);

    const int tid  = threadIdx.x;
    const int w    = tid >> 5;
    const int lane = tid & 31;
    const int quad = lane >> 3;
    const int l4   = lane >> 2;
    const int l2   = (lane & 3) << 1;
    const int r0   = blockIdx.x * 128;

    const uint32_t Xh_u = (uint32_t)__cvta_generic_to_shared(Xh);
    const uint32_t Xl_u = (uint32_t)__cvta_generic_to_shared(Xl);
    const uint32_t Wh_u = (uint32_t)__cvta_generic_to_shared(Wh);
    const uint32_t Wl_u = (uint32_t)__cvta_generic_to_shared(Wl);
    const uint32_t xf_u[2] = {(uint32_t)__cvta_generic_to_shared(psm + PX0),
                              (uint32_t)__cvta_generic_to_shared(psm + PX1)};
    const uint32_t wf_u[2] = {(uint32_t)__cvta_generic_to_shared(psm + PW0),
                              (uint32_t)__cvta_generic_to_shared(psm + PW1)};
    const float* xf_p[2] = {(const float*)(psm + PX0), (const float*)(psm + PX1)};
    const float* wf_p[2] = {(const float*)(psm + PW0), (const float*)(psm + PW1)};

    const uint32_t xa = ((16 * w + 8 * (quad & 1) + (lane & 7)) * QS + 8 * (quad >> 1)) * 2;
    const uint32_t wb = ((8 * (quad & 1) + (lane & 7)) * QS + 8 * (quad >> 1)) * 2;

    float Oacc[8][4];
#pragma unroll
    for (int nb = 0; nb < 8; nb++)
#pragma unroll
        for (int j = 0; j < 4; j++) Oacc[nb][j] = 0.f;

    {
#pragma unroll
        for (int u = 0; u < 8; u++) {
            int e = tid + u * 256;
            int row = e >> 4, c4 = e & 15;
            cpa16(xf_u[0] + (uint32_t)(row * 64 + c4 * 4) * 4,
                  &x[(size_t)(r0 + row) * NC + c4 * 4]);
        }
#pragma unroll
        for (int u = 0; u < 4; u++) {
            int e = tid + u * 256;
            int row = e >> 4, c4 = e & 15;
            cpa16(wf_u[0] + (uint32_t)(row * 64 + c4 * 4) * 4,
                  &Wq[(size_t)row * NH + c4 * 4]);
        }
        CPA_COMMIT();
    }

    for (int ci = 0; ci < 12; ci++) {
        CPA_WAIT0();
        __syncthreads();
        if (ci + 1 < 12) {
            const int c0n = (ci + 1) * 64;
            const int nb_ = (ci + 1) & 1;
#pragma unroll
            for (int u = 0; u < 8; u++) {
                int e = tid + u * 256;
                int row = e >> 4, c4 = e & 15;
                cpa16(xf_u[nb_] + (uint32_t)(row * 64 + c4 * 4) * 4,
                      &x[(size_t)(r0 + row) * NC + c0n + c4 * 4]);
            }
#pragma unroll
            for (int u = 0; u < 4; u++) {
                int e = tid + u * 256;
                int row = e >> 4, c4 = e & 15;
                cpa16(wf_u[nb_] + (uint32_t)(row * 64 + c4 * 4) * 4,
                      &Wq[(size_t)(c0n + row) * NH + c4 * 4]);
            }
            CPA_COMMIT();
        }

        const float* Xc = xf_p[ci & 1];
        const float* Wc = wf_p[ci & 1];
#pragma unroll
        for (int u = 0; u < 8; u++) {
            int e = tid + u * 256;
            int row = e >> 4, g4 = e & 15;
            float4 v = *(const float4*)&Xc[row * 64 + g4 * 4];
            uint32_t h0 = packbf(v.x, v.y);
            uint32_t h1 = packbf(v.z, v.w);
            uint32_t l0 = packbf(v.x - __uint_as_float(h0 << 16),
                                 v.y - __uint_as_float(h0 & 0xffff0000u));
            uint32_t l1 = packbf(v.z - __uint_as_float(h1 << 16),
                                 v.w - __uint_as_float(h1 & 0xffff0000u));
            *(uint2*)&Xh[row * QS + g4 * 4] = make_uint2(h0, h1);
            *(uint2*)&Xl[row * QS + g4 * 4] = make_uint2(l0, l1);
        }
#pragma unroll
        for (int u = 0; u < 4; u++) {
            int e = tid + u * 256;
            int row = e >> 4, g4 = e & 15;
            float4 v = *(const float4*)&Wc[row * 64 + g4 * 4];
            uint32_t h0 = packbf(v.x, v.y);
            uint32_t h1 = packbf(v.z, v.w);
            uint32_t l0 = packbf(v.x - __uint_as_float(h0 << 16),
                                 v.y - __uint_as_float(h0 & 0xffff0000u));
            uint32_t l1 = packbf(v.z - __uint_as_float(h1 << 16),
                                 v.w - __uint_as_float(h1 & 0xffff0000u));
            *(uint2*)&Wh[row * QS + g4 * 4] = make_uint2(h0, h1);
            *(uint2*)&Wl[row * QS + g4 * 4] = make_uint2(l0, l1);
        }
        __syncthreads();

        uint32_t ah[4][4], al[4][4];
#pragma unroll
        for (int ks = 0; ks < 4; ks++) {
            ldsm4(ah[ks], Xh_u + xa + 32 * ks);
            ldsm4(al[ks], Xl_u + xa + 32 * ks);
        }
#pragma unroll
        for (int ks = 0; ks < 4; ks++) {
#pragma unroll
            for (int nbp = 0; nbp < 4; nbp++) {
                uint32_t off = wb + (16 * ks * QS + 16 * nbp) * 2;
                uint32_t bh[4], bl[4];
                ldsm4t(bh, Wh_u + off);
                ldsm4t(bl, Wl_u + off);
                mma_bf16(Oacc[2 * nbp],     ah[ks], bh[0], bh[1]);
                mma_bf16(Oacc[2 * nbp + 1], ah[ks], bh[2], bh[3]);
                mma_bf16(Oacc[2 * nbp],     ah[ks], bl[0], bl[1]);
                mma_bf16(Oacc[2 * nbp + 1], ah[ks], bl[2], bl[3]);
                mma_bf16(Oacc[2 * nbp],     al[ks], bh[0], bh[1]);
                mma_bf16(Oacc[2 * nbp + 1], al[ks], bh[2], bh[3]);
            }
        }
    }

    const size_t row0 = (size_t)r0 + 16 * w + l4;
#pragma unroll
    for (int nb = 0; nb < 8; nb++) {
        int c = 8 * nb + l2;
        uint32_t hp0 = packbf(Oacc[nb][0], Oacc[nb][1]);
        uint32_t hp1 = packbf(Oacc[nb][2], Oacc[nb][3]);
        uint32_t lp0 = packbf(Oacc[nb][0] - __uint_as_float(hp0 << 16),
                              Oacc[nb][1] - __uint_as_float(hp0 & 0xffff0000u));
        uint32_t lp1 = packbf(Oacc[nb][2] - __uint_as_float(hp1 << 16),
                              Oacc[nb][3] - __uint_as_float(hp1 & 0xffff0000u));
        *(uint32_t*)&g_qh[row0 * NH + c]       = hp0;
        *(uint32_t*)&g_ql[row0 * NH + c]       = lp0;
        *(uint32_t*)&g_qh[(row0 + 8) * NH + c] = hp1;
        *(uint32_t*)&g_ql[(row0 + 8) * NH + c] = lp1;
    }
}

// ---------------------------------------------------------------------------
// Flash attention: R13 skeleton (pair-scheduled, 2 groups, in-kernel merge)
// + software pipeline: QK(it+1) issued BEFORE softmax(it) so the tensor pipe
// executes next tile's QK under the MUFU/pack chain. Triple-buffered K via
// cp.async; two score register sets (sa/sb) ping-pong via 2x-unrolled loop.
// ---------------------------------------------------------------------------
#define SM_Q      0         // Qh+Ql 18432; reused as merge scratch at tile end
#define SM_REL    18432     // 16384
#define SM_GRP0   34816
#define SM_KBUF   18432     // one buffer: Kh 9216 + Kl 9216
#define SM_GRPSZ  (3 * SM_KBUF)
#define SMEM_BYTES (SM_GRP0 + 2 * SM_GRPSZ)   // 145408

#define QK_TILE(SN, KBASE)                                                     \
    {                                                                          \
        const uint32_t Kh_u_ = (KBASE);                                        \
        const uint32_t Kl_u_ = (KBASE) + 9216;                                 \
        _Pragma("unroll")                                                      \
        for (int nb = 0; nb < 8; nb++)                                         \
            _Pragma("unroll")                                                  \
            for (int j = 0; j < 4; j++) SN[nb][j] = 0.f;                       \
        _Pragma("unroll")                                                      \
        for (int ks = 0; ks < 4; ks++) {                                       \
            _Pragma("unroll")                                                  \
            for (int nbp = 0; nbp < 4; nbp++) {                                \
                uint32_t off = kqk + (16 * nbp * QS + 16 * ks) * 2;            \
                uint32_t bh[4], bl[4];                                         \
                ldsm4(bh, Kh_u_ + off);                                        \
                ldsm4(bl, Kl_u_ + off);                                        \
                mma_bf16(SN[2 * nbp],     qfh[ks], bh[0], bh[1]);              \
                mma_bf16(SN[2 * nbp + 1], qfh[ks], bh[2], bh[3]);              \
                mma_bf16(SN[2 * nbp],     qfh[ks], bl[0], bl[1]);              \
                mma_bf16(SN[2 * nbp + 1], qfh[ks], bl[2], bl[3]);              \
                mma_bf16(SN[2 * nbp],     qfl[ks], bh[0], bh[1]);              \
                mma_bf16(SN[2 * nbp + 1], qfl[ks], bh[2], bh[3]);              \
            }                                                                  \
        }                                                                      \
    }

#define FLASH_ITER(IT, SC, SN)                                                 \
    {                                                                          \
        const int kt_ = g + 2 * (IT);                                          \
        const int s0_ = kt_ * 64;                                              \
        CPA_WAIT0();                                                           \
        asm volatile("bar.sync %0, %1;" :: "r"(1 + g), "r"(128) : "memory");   \
        if ((IT) + 2 < nit) {                                                  \
            const int s0n_ = s0_ + 256;                                        \
            _Pragma("unroll")                                                  \
            for (int u = 0; u < 4; u++) {                                      \
                int e = tid128 + u * 128;                                      \
                int row = e >> 3, q4 = e & 7;                                  \
                uint32_t off = (uint32_t)(row * QS + q4 * 8) * 2;              \
                cpa16(kpre + off,        gkh + (size_t)(s0n_ + row) * NH + q4 * 8); \
                cpa16(kpre + 9216 + off, gkl + (size_t)(s0n_ + row) * NH + q4 * 8); \
            }                                                                  \
            CPA_COMMIT();                                                      \
        }                                                                      \
        if ((IT) + 1 < nit) QK_TILE(SN, knxt);                                 \
        /* softmax(it) on SC */                                                \
        {                                                                      \
            const bool diag = (kt_ == tile);                                   \
            const int bb0 = s0_ - t0 + 2047 - rbase;                           \
            const int bb1 = bb0 - 8;                                           \
            _Pragma("unroll")                                                  \
            for (int nb = 0; nb < 8; nb++) {                                   \
                int c0 = 8 * nb + l2;                                          \
                float p0 = ex2(fmaf(SC[nb][0], SCLG, rel_sh[bb0 + c0]));       \
                float p1 = ex2(fmaf(SC[nb][1], SCLG, rel_sh[bb0 + c0 + 1]));   \
                float p2 = ex2(fmaf(SC[nb][2], SCLG, rel_sh[bb1 + c0]));       \
                float p3 = ex2(fmaf(SC[nb][3], SCLG, rel_sh[bb1 + c0 + 1]));   \
                if (diag) {                                                    \
                    if (c0 > rbase)         p0 = 0.f;                          \
                    if (c0 + 1 > rbase)     p1 = 0.f;                          \
                    if (c0 > rbase + 8)     p2 = 0.f;                          \
                    if (c0 + 1 > rbase + 8) p3 = 0.f;                          \
                }                                                              \
                SC[nb][0] = p0; SC[nb][1] = p1; SC[nb][2] = p2; SC[nb][3] = p3;\
                lrow[0] += p0 + p1;                                            \
                lrow[1] += p2 + p3;                                            \
            }                                                                  \
        }                                                                      \
        /* PV(it) on SC using kcur */                                          \
        {                                                                      \
            const uint32_t Kh_u_ = kcur;                                       \
            const uint32_t Kl_u_ = kcur + 9216;                                \
            _Pragma("unroll")                                                  \
            for (int kb = 0; kb < 4; kb++) {                                   \
                uint32_t pah[4], pal[4];                                       \
                {                                                              \
                    float p0 = SC[2 * kb][0],     p1 = SC[2 * kb][1];          \
                    float p2 = SC[2 * kb][2],     p3 = SC[2 * kb][3];          \
                    float p4 = SC[2 * kb + 1][0], p5 = SC[2 * kb + 1][1];      \
                    float p6 = SC[2 * kb + 1][2], p7 = SC[2 * kb + 1][3];      \
                    pah[0] = packbf(p0, p1); pah[1] = packbf(p2, p3);          \
                    pah[2] = packbf(p4, p5); pah[3] = packbf(p6, p7);          \
                    pal[0] = packbf(p0 - __uint_as_float(pah[0] << 16),        \
                                    p1 - __uint_as_float(pah[0] & 0xffff0000u)); \
                    pal[1] = packbf(p2 - __uint_as_float(pah[1] << 16),        \
                                    p3 - __uint_as_float(pah[1] & 0xffff0000u)); \
                    pal[2] = packbf(p4 - __uint_as_float(pah[2] << 16),        \
                                    p5 - __uint_as_float(pah[2] & 0xffff0000u)); \
                    pal[3] = packbf(p6 - __uint_as_float(pah[3] << 16),        \
                                    p7 - __uint_as_float(pah[3] & 0xffff0000u)); \
                }                                                              \
                _Pragma("unroll")                                              \
                for (int nbp = 0; nbp < 4; nbp++) {                            \
                    uint32_t off = kpv + (16 * kb * QS + 16 * nbp) * 2;        \
                    uint32_t vh[4], vl[4];                                     \
                    ldsm4t(vh, Kh_u_ + off);                                   \
                    ldsm4t(vl, Kl_u_ + off);                                   \
                    mma_bf16(Oa[2 * nbp],     pah, vh[0], vh[1]);              \
                    mma_bf16(Oa[2 * nbp + 1], pah, vh[2], vh[3]);              \
                    mma_bf16(Oa[2 * nbp],     pah, vl[0], vl[1]);              \
                    mma_bf16(Oa[2 * nbp + 1], pah, vl[2], vl[3]);              \
                    mma_bf16(Oa[2 * nbp],     pal, vh[0], vh[1]);              \
                    mma_bf16(Oa[2 * nbp + 1], pal, vh[2], vh[3]);              \
                }                                                              \
            }                                                                  \
        }                                                                      \
        { uint32_t t_ = kcur; kcur = knxt; knxt = kpre; kpre = t_; }           \
    }

__global__ __launch_bounds__(256) void flashT_kernel(const float* __restrict__ rel,
                                                     float* __restrict__ out) {
    extern __shared__ char smraw[];
    __nv_bfloat16* Qh = (__nv_bfloat16*)(smraw + SM_Q);
    __nv_bfloat16* Ql = Qh + 64 * QS;
    float* rel_sh = (float*)(smraw + SM_REL);

    const int tid  = threadIdx.x;
    const int w    = tid >> 5;
    const int lane = tid & 31;
    const int g    = w >> 2;
    const int wi   = w & 3;
    const int quad = lane >> 3;
    const int l4   = lane >> 2;
    const int l2   = (lane & 3) << 1;
    const int tid128 = tid & 127;

    char* gbase = smraw + SM_GRP0 + g * SM_GRPSZ;

    float* Om = (float*)(smraw + SM_Q);            // [64][65] merge scratch
    float* Lm = (float*)(smraw + SM_Q + 16640);    // [64]

    const uint32_t Qh_u = (uint32_t)__cvta_generic_to_shared(Qh);
    const uint32_t Ql_u = (uint32_t)__cvta_generic_to_shared(Ql);

    const uint32_t qa  = ((16 * wi + 8 * (quad & 1) + (lane & 7)) * QS + 8 * (quad >> 1)) * 2;
    const uint32_t kqk = ((8 * (quad >> 1) + (lane & 7)) * QS + 8 * (quad & 1)) * 2;
    const uint32_t kpv = ((8 * (quad & 1) + (lane & 7)) * QS + 8 * (quad >> 1)) * 2;

    const int b    = blockIdx.y;
    const int pair = blockIdx.x;
    const int rbase = 16 * wi + l4;

    for (int i = tid; i < 4095; i += 256) rel_sh[i] = rel[i] * LOG2E;

    const __nv_bfloat16* gkh = &g_qh[(size_t)b * NT * NH];
    const __nv_bfloat16* gkl = &g_ql[(size_t)b * NT * NH];

    for (int pi = 0; pi < 2; pi++) {
        const int tile = (pi == 0) ? (31 - pair) : pair;
        const int t0   = tile * 64;
        __syncthreads();
        // stage Q hi/lo
        {
            const __nv_bfloat16* sh = gkh + (size_t)t0 * NH;
            const __nv_bfloat16* sl = gkl + (size_t)t0 * NH;
#pragma unroll
            for (int u = 0; u < 2; u++) {
                int e   = tid + u * 256;
                int row = e >> 3, q4 = e & 7;
                *(uint4*)&Qh[row * QS + q4 * 8] = *(const uint4*)&sh[row * 64 + q4 * 8];
                *(uint4*)&Ql[row * QS + q4 * 8] = *(const uint4*)&sl[row * 64 + q4 * 8];
            }
        }
        __syncthreads();

        uint32_t qfh[4][4], qfl[4][4];
#pragma unroll
        for (int ks = 0; ks < 4; ks++) {
            ldsm4(qfh[ks], Qh_u + qa + 32 * ks);
            ldsm4(qfl[ks], Ql_u + qa + 32 * ks);
        }

        float Oa[8][4];
#pragma unroll
        for (int nb = 0; nb < 8; nb++)
#pragma unroll
            for (int j = 0; j < 4; j++) Oa[nb][j] = 0.f;
        float lrow[2] = {0.f, 0.f};
        float sa[8][4], sb[8][4];

        const int nit = (g <= tile) ? (((tile - g) >> 1) + 1) : 0;

        uint32_t kcur = (uint32_t)__cvta_generic_to_shared(gbase);
        uint32_t knxt = kcur + SM_KBUF;
        uint32_t kpre = kcur + 2 * SM_KBUF;

        if (nit > 0) {
            const int s00 = g * 64;
#pragma unroll
            for (int u = 0; u < 4; u++) {
                int e = tid128 + u * 128;
                int row = e >> 3, q4 = e & 7;
                uint32_t off = (uint32_t)(row * QS + q4 * 8) * 2;
                cpa16(kcur + off,        gkh + (size_t)(s00 + row) * NH + q4 * 8);
                cpa16(kcur + 9216 + off, gkl + (size_t)(s00 + row) * NH + q4 * 8);
            }
            CPA_COMMIT();
            if (nit > 1) {
                const int s01 = s00 + 128;
#pragma unroll
                for (int u = 0; u < 4; u++) {
                    int e = tid128 + u * 128;
                    int row = e >> 3, q4 = e & 7;
                    uint32_t off = (uint32_t)(row * QS + q4 * 8) * 2;
                    cpa16(knxt + off,        gkh + (size_t)(s01 + row) * NH + q4 * 8);
                    cpa16(knxt + 9216 + off, gkl + (size_t)(s01 + row) * NH + q4 * 8);
                }
                CPA_COMMIT();
                CPA_WAIT1();
            } else {
                CPA_WAIT0();
            }
            asm volatile("bar.sync %0, %1;" :: "r"(1 + g), "r"(128) : "memory");
            QK_TILE(sa, kcur);
        }

        int it = 0;
        while (it < nit) {
            FLASH_ITER(it, sa, sb); it++;
            if (it < nit) { FLASH_ITER(it, sb, sa); it++; }
        }

        // reduce row sums over the 4 lanes sharing a row
        lrow[0] += __shfl_xor_sync(0xffffffffu, lrow[0], 1);
        lrow[0] += __shfl_xor_sync(0xffffffffu, lrow[0], 2);
        lrow[1] += __shfl_xor_sync(0xffffffffu, lrow[1], 1);
        lrow[1] += __shfl_xor_sync(0xffffffffu, lrow[1], 2);

        // ---- merge the two groups' partials (pure addition), write out ----
        __syncthreads();
        if (g == 1) {
#pragma unroll
            for (int nb = 0; nb < 8; nb++) {
                Om[rbase * 65 + 8 * nb + l2]           = Oa[nb][0];
                Om[rbase * 65 + 8 * nb + l2 + 1]       = Oa[nb][1];
                Om[(rbase + 8) * 65 + 8 * nb + l2]     = Oa[nb][2];
                Om[(rbase + 8) * 65 + 8 * nb + l2 + 1] = Oa[nb][3];
            }
            if ((lane & 3) == 0) {
                Lm[rbase]     = lrow[0];
                Lm[rbase + 8] = lrow[1];
            }
        }
        __syncthreads();
        if (g == 0) {
#pragma unroll
            for (int half = 0; half < 2; half++) {
                const int row = rbase + 8 * half;
                const float inv = 1.f / (lrow[half] + Lm[row]);
                float* orow = &out[((size_t)b * NT + t0 + row) * NH];
#pragma unroll
                for (int nb = 0; nb < 8; nb++) {
                    int c = 8 * nb + l2;
                    float2 o2;
                    o2.x = (Oa[nb][2 * half]     + Om[row * 65 + c])     * inv;
                    o2.y = (Oa[nb][2 * half + 1] + Om[row * 65 + c + 1]) * inv;
                    *(float2*)&orow[c] = o2;
                }
            }
        }
    }
}

extern "C" void kernel_launch(void* const* d_in, const int* in_sizes, int n_in,
                              void* d_out, int out_size) {
    const float* x   = (const float*)d_in[0];
    const float* Wq  = (const float*)d_in[1];
    const float* rel = (const float*)d_in[2];
    float* out = (float*)d_out;

    static bool attr_set = false;
    if (!attr_set) {
        cudaFuncSetAttribute(flashT_kernel,
                             cudaFuncAttributeMaxDynamicSharedMemorySize, SMEM_BYTES);
        cudaFuncSetAttribute(projT_kernel,
                             cudaFuncAttributeMaxDynamicSharedMemorySize, PSMEM);
        attr_set = true;
    }

    projT_kernel<<<NB * NT / 128, 256, PSMEM>>>(x, Wq);

    dim3 grid(16, NB);
    flashT_kernel<<<grid, 256, SMEM_BYTES>>>(rel, out);
}